// round 16
// baseline (speedup 1.0000x reference)
#include <cuda_runtime.h>
#include <math.h>
#include <stdint.h>

// Problem constants: B=16, SEG=512, MEM=512, TOTAL=1024, MD=128, H=8, D=128

// ---------------- scratch ----------------
__device__ float g_qf  [16 * 512 * 1024];          // x@Wq              32 MB
__device__ float g_kvf [16 * 1024 * 2048];         // h@Wkv            128 MB
__device__ float g_rf  [1024 * 1024];              // R@Wr               4 MB
__device__ float g_g   [128ll * 512 * 1024];       // G=(q+u2)@r^T     256 MB
__device__ float g_att [16 * 512 * 1024];          // attention out     32 MB
__device__ float g_part[4 * 8192 * 128];           // Wmlp split-K partials 16 MB

// ---------------- helpers ----------------
__device__ __forceinline__ uint32_t f2tf(float f) {
    uint32_t u; asm("cvt.rna.tf32.f32 %0, %1;" : "=r"(u) : "f"(f)); return u;
}
__device__ __forceinline__ void mma8(float4& c, const uint32_t a[4], uint32_t b0, uint32_t b1) {
    asm volatile("mma.sync.aligned.m16n8k8.row.col.f32.tf32.tf32.f32 "
        "{%0,%1,%2,%3}, {%4,%5,%6,%7}, {%8,%9}, {%0,%1,%2,%3};"
        : "+f"(c.x), "+f"(c.y), "+f"(c.z), "+f"(c.w)
        : "r"(a[0]), "r"(a[1]), "r"(a[2]), "r"(a[3]), "r"(b0), "r"(b1));
}
__device__ __forceinline__ void cpa16(uint32_t saddr, const void* g) {
    asm volatile("cp.async.cg.shared.global [%0], [%1], 16;" :: "r"(saddr), "l"(g));
}
__device__ __forceinline__ void cpa_commit() {
    asm volatile("cp.async.commit_group;");
}
template <int N> __device__ __forceinline__ void cpa_wait() {
    asm volatile("cp.async.wait_group %0;" :: "n"(N));
}

// ---------------- gemm3: kvf | qf | rf, cp.async 2-stage (K=128, tile 128x128, BK=32) ----------------
#define G3_SMEM 70656
__global__ __launch_bounds__(256) void gemm3(
    const float* __restrict__ x, const float* __restrict__ mem, const float* __restrict__ R,
    const float* __restrict__ Wq, const float* __restrict__ Wkv, const float* __restrict__ Wr,
    float* __restrict__ qf, float* __restrict__ kvf, float* __restrict__ rf)
{
    extern __shared__ uint32_t sh[];
    const uint32_t sbase = (uint32_t)__cvta_generic_to_shared(sh);

    const int tid = threadIdx.x, lane = tid & 31, wid = tid >> 5;
    const int g = lane >> 2, lt = lane & 3;
    const int wm = (wid & 1) << 6;
    const int wn = (wid >> 1) << 5;
    const int am = tid >> 3, ak = (tid & 7) << 2;
    const int bk = tid >> 5, bn = (tid & 31) << 2;

    const int bid = blockIdx.x;
    int N, m0, n0;
    const float* Bw;
    float* C;
    const float* aptr[4];

    if (bid < 2048) {                       // kvf = concat(mem,x) @ Wkv
        N = 2048; Bw = Wkv; C = kvf;
        m0 = (bid >> 4) << 7; n0 = (bid & 15) << 7;
#pragma unroll
        for (int it = 0; it < 4; it++) {
            int row = m0 + am + (it << 5);
            int b = row >> 10, loc = row & 1023;
            aptr[it] = (loc < 512) ? (mem + (long)b * 65536 + (long)loc * 128)
                                   : (x   + (long)b * 65536 + (long)(loc - 512) * 128);
        }
    } else if (bid < 2560) {                // qf = x @ Wq
        int t = bid - 2048;
        N = 1024; Bw = Wq; C = qf;
        m0 = (t >> 3) << 7; n0 = (t & 7) << 7;
#pragma unroll
        for (int it = 0; it < 4; it++)
            aptr[it] = x + (long)(m0 + am + (it << 5)) * 128;
    } else {                                // rf = R @ Wr
        int t = bid - 2560;
        N = 1024; Bw = Wr; C = rf;
        m0 = (t >> 3) << 7; n0 = (t & 7) << 7;
#pragma unroll
        for (int it = 0; it < 4; it++)
            aptr[it] = R + (long)(m0 + am + (it << 5)) * 128;
    }

    auto stage = [&](int p, int k0) {
#pragma unroll
        for (int it = 0; it < 4; it++) {
            cpa16(sbase + p * 18432 + ((am + (it << 5)) * 36 + ak) * 4,
                  aptr[it] + k0 + ak);
            cpa16(sbase + 36864 + p * 16896 + ((bk + (it << 3)) * 132 + bn) * 4,
                  Bw + (long)(k0 + bk + (it << 3)) * N + n0 + bn);
        }
        cpa_commit();
    };

    float4 acc[4][4];
#pragma unroll
    for (int t = 0; t < 4; t++)
#pragma unroll
        for (int s = 0; s < 4; s++) acc[t][s] = make_float4(0.f, 0.f, 0.f, 0.f);

    stage(0, 0);
#pragma unroll
    for (int kq = 0; kq < 4; kq++) {
        if (kq < 3) { stage((kq + 1) & 1, (kq + 1) << 5); cpa_wait<1>(); }
        else        { cpa_wait<0>(); }
        __syncthreads();
        const uint32_t* Ac = sh + (kq & 1) * 4608;
        const uint32_t* Bc = sh + 9216 + (kq & 1) * 4224;
#pragma unroll
        for (int kk = 0; kk < 4; kk++) {
            const int kb = kk << 3;
            uint32_t af[4][4];
#pragma unroll
            for (int t = 0; t < 4; t++) {
                int row = wm + (t << 4) + g;
                af[t][0] = Ac[row * 36 + kb + lt];
                af[t][1] = Ac[(row + 8) * 36 + kb + lt];
                af[t][2] = Ac[row * 36 + kb + lt + 4];
                af[t][3] = Ac[(row + 8) * 36 + kb + lt + 4];
            }
#pragma unroll
            for (int s = 0; s < 4; s++) {
                int col = wn + (s << 3) + g;
                uint32_t b0 = Bc[(kb + lt) * 132 + col];
                uint32_t b1 = Bc[(kb + lt + 4) * 132 + col];
#pragma unroll
                for (int t = 0; t < 4; t++) mma8(acc[t][s], af[t], b0, b1);
            }
        }
        __syncthreads();
    }

#pragma unroll
    for (int t = 0; t < 4; t++) {
        int r0 = m0 + wm + (t << 4) + g;
#pragma unroll
        for (int s = 0; s < 4; s++) {
            int c = n0 + wn + (s << 3) + (lt << 1);
            *(float2*)(C + (long)r0 * N + c) = make_float2(acc[t][s].x, acc[t][s].y);
            *(float2*)(C + (long)(r0 + 8) * N + c) = make_float2(acc[t][s].z, acc[t][s].w);
        }
    }
}

// ---------------- G = (q + u2) @ r^T, cp.async 2-stage ----------------
#define GNT_SMEM 73728
__global__ __launch_bounds__(256) void gemm_nt_g(
    const float* __restrict__ qf, const float* __restrict__ rf,
    const float* __restrict__ U2, float* __restrict__ Gg)
{
    const int r0 = blockIdx.y << 7, c0 = blockIdx.x << 7;
    if (r0 + c0 + 254 < 511) return;     // never-used region of G
    const int z = blockIdx.z, h = z & 7;
    const float* A  = qf + (long)z * 65536;
    const float* Bm = rf + (long)h * 131072;
    float*       G  = Gg + (long)z * 524288;

    extern __shared__ uint32_t sh[];
    const uint32_t sbase = (uint32_t)__cvta_generic_to_shared(sh);
    __shared__ float u2s[128];

    const int tid = threadIdx.x, lane = tid & 31, wid = tid >> 5;
    const int wm = (wid & 1) << 6;
    const int wn = (wid >> 1) << 5;
    const int g = lane >> 2, lt = lane & 3;
    const int am = tid >> 3, ak = (tid & 7) << 2;

    if (tid < 128) u2s[tid] = U2[(h << 7) + tid];

    auto stage = [&](int p, int k0) {
#pragma unroll
        for (int it = 0; it < 4; it++) {
            cpa16(sbase + p * 18432 + ((am + (it << 5)) * 36 + ak) * 4,
                  A + (long)(r0 + am + (it << 5)) * 128 + k0 + ak);
            cpa16(sbase + 36864 + p * 18432 + ((am + (it << 5)) * 36 + ak) * 4,
                  Bm + (long)(c0 + am + (it << 5)) * 128 + k0 + ak);
        }
        cpa_commit();
    };

    float4 acc[4][4];
#pragma unroll
    for (int t = 0; t < 4; t++)
#pragma unroll
        for (int s = 0; s < 4; s++) acc[t][s] = make_float4(0.f, 0.f, 0.f, 0.f);

    stage(0, 0);
#pragma unroll
    for (int kq = 0; kq < 4; kq++) {
        const int k0 = kq << 5;
        if (kq < 3) { stage((kq + 1) & 1, (kq + 1) << 5); cpa_wait<1>(); }
        else        { cpa_wait<0>(); }
        __syncthreads();
        const uint32_t* Ac = sh + (kq & 1) * 4608;
        const uint32_t* Bc = sh + 9216 + (kq & 1) * 4608;
#pragma unroll
        for (int kk = 0; kk < 4; kk++) {
            const int kb = kk << 3;
            float uLo = u2s[k0 + kb + lt], uHi = u2s[k0 + kb + lt + 4];
            uint32_t af[4][4];
#pragma unroll
            for (int t = 0; t < 4; t++) {
                int row = wm + (t << 4) + g;
                af[t][0] = f2tf(__uint_as_float(Ac[row * 36 + kb + lt]) + uLo);
                af[t][1] = f2tf(__uint_as_float(Ac[(row + 8) * 36 + kb + lt]) + uLo);
                af[t][2] = f2tf(__uint_as_float(Ac[row * 36 + kb + lt + 4]) + uHi);
                af[t][3] = f2tf(__uint_as_float(Ac[(row + 8) * 36 + kb + lt + 4]) + uHi);
            }
#pragma unroll
            for (int s = 0; s < 4; s++) {
                int n = (wn + (s << 3) + g) * 36 + kb + lt;
                uint32_t b0 = Bc[n], b1 = Bc[n + 4];
#pragma unroll
                for (int t = 0; t < 4; t++) mma8(acc[t][s], af[t], b0, b1);
            }
        }
        __syncthreads();
    }

#pragma unroll
    for (int t = 0; t < 4; t++) {
        int rr = r0 + wm + (t << 4) + g;
#pragma unroll
        for (int s = 0; s < 4; s++) {
            int c = c0 + wn + (s << 3) + (lt << 1);
            *(float2*)(G + (long)rr * 1024 + c) = make_float2(acc[t][s].x, acc[t][s].y);
            *(float2*)(G + (long)(rr + 8) * 1024 + c) = make_float2(acc[t][s].z, acc[t][s].w);
        }
    }
}

// ---------------- fused flash: S=(q+u1)K^T + gather(G) -> online softmax -> P@V ----------------
// Grid (8 i-tiles, 128 z); 128 threads / 4 warps; warp owns 16 full rows.
// 3 syncs/iter; K(jt+1) issued right after AC; G rows prefetched above AC mma.
// Smem: Ps[64][68] @0 (17408) | Ks[64][132] @17408 (33792) | Vs[64][136] @51200 (34816). 86016 B.
#define FLASH_SMEM 86016

__global__ __launch_bounds__(128) void flash_pv(
    const float* __restrict__ qf, const float* __restrict__ kvf,
    const float* __restrict__ Gg, const float* __restrict__ U1,
    float* __restrict__ att)
{
    extern __shared__ char dsm[];
    uint32_t* Ps = (uint32_t*)dsm;                  // [64][68]
    uint32_t* Ks = (uint32_t*)(dsm + 17408);        // [64][132]
    uint32_t* Vs = (uint32_t*)(dsm + 51200);        // [64][136]
    const uint32_t ks_s = (uint32_t)__cvta_generic_to_shared(Ks);
    const uint32_t vs_s = (uint32_t)__cvta_generic_to_shared(Vs);

    const int it = 7 - blockIdx.x;                  // heavy tiles first
    const int z = blockIdx.y, h = z & 7;
    const int i0 = it << 6;
    const float* Q  = qf  + (long)z * 65536;
    const float* Kg = kvf + (long)z * 131072;
    const float* Vg = kvf + 16777216L + (long)z * 131072;
    const float* Gz = Gg  + (long)z * 524288;
    const float* u1 = U1  + (h << 7);

    const int tid = threadIdx.x, lane = tid & 31, w = tid >> 5;
    const int g = lane >> 2, lt = lane & 3;
    const int wm = w << 4;
    const int iA = i0 + wm + g, iB = iA + 8;

    const int sr = tid >> 1, sc0 = (tid & 1) << 2;  // staging: 64 rows, 2 thr/row

    // prologue: async-stage K(0)
#pragma unroll
    for (int f = 0; f < 16; f++) {
        int k = sc0 + (f << 3);
        cpa16(ks_s + (sr * 132 + k) * 4, Kg + (long)sr * 128 + k);
    }
    cpa_commit();

    // resident (q+u1) A-fragments
    uint32_t Qreg[64];
#pragma unroll
    for (int kc = 0; kc < 16; kc++) {
        int k0 = kc << 3;
        float ua = u1[k0 + lt], ub = u1[k0 + lt + 4];
        Qreg[kc * 4 + 0] = f2tf(Q[(long)iA * 128 + k0 + lt] + ua);
        Qreg[kc * 4 + 1] = f2tf(Q[(long)iB * 128 + k0 + lt] + ua);
        Qreg[kc * 4 + 2] = f2tf(Q[(long)iA * 128 + k0 + lt + 4] + ub);
        Qreg[kc * 4 + 3] = f2tf(Q[(long)iB * 128 + k0 + lt + 4] + ub);
    }

    float4 on[16];
#pragma unroll
    for (int n = 0; n < 16; n++) on[n] = make_float4(0.f, 0.f, 0.f, 0.f);
    float mA = -1e30f, mB = -1e30f, lA = 0.f, lB = 0.f;

    const float inv = 0.08838834764831845f;         // 1/sqrt(128)
    const float* GA = Gz + (long)iA * 1024 + 511 - iA;
    const float* GB = Gz + (long)iB * 1024 + 511 - iB;
    const int capA = iA + 512, capB = iB + 512;
    const int njt = it + 9;

    for (int jt = 0; jt < njt; jt++) {
        const int j0 = jt << 6;

        cpa_wait<0>();                              // K(jt) complete (only group outstanding)
        __syncthreads();                            // (1) prev PV done (Vs free) + Ks visible

        // issue V(jt) async — overlaps AC mma
#pragma unroll
        for (int f = 0; f < 16; f++) {
            int c = sc0 + (f << 3);
            cpa16(vs_s + (sr * 136 + c) * 4, Vg + (long)(j0 + sr) * 128 + c);
        }
        cpa_commit();

        // prefetch G rows (guarded) — latency hidden under AC mma
        float2 ga[8], gb[8];
#pragma unroll
        for (int s = 0; s < 8; s++) {
            int j = j0 + (s << 3) + (lt << 1);
            ga[s].x = (j     <= capA) ? GA[j]     : 0.f;
            ga[s].y = (j + 1 <= capA) ? GA[j + 1] : 0.f;
            gb[s].x = (j     <= capB) ? GB[j]     : 0.f;
            gb[s].y = (j + 1 <= capB) ? GB[j + 1] : 0.f;
        }

        // ---- AC mma ----
        float4 acS[8];
#pragma unroll
        for (int s = 0; s < 8; s++) acS[s] = make_float4(0.f, 0.f, 0.f, 0.f);
#pragma unroll
        for (int kc = 0; kc < 16; kc++) {
            const uint32_t* a = &Qreg[kc << 2];
            int kb = kc << 3;
#pragma unroll
            for (int s = 0; s < 8; s++) {
                int n = ((s << 3) + g) * 132 + kb + lt;
                mma8(acS[s], a, Ks[n], Ks[n + 4]);
            }
        }

        __syncthreads();                            // (2) all warps done reading Ks
        if (jt + 1 < njt) {                         // issue K(jt+1) — overlaps softmax + PV
            const int jn = (jt + 1) << 6;
#pragma unroll
            for (int f = 0; f < 16; f++) {
                int k = sc0 + (f << 3);
                cpa16(ks_s + (sr * 132 + k) * 4, Kg + (long)(jn + sr) * 128 + k);
            }
            cpa_commit();
        }

        // ---- add G, scale, mask; row max ----
        float mxA = -1e30f, mxB = -1e30f;
#pragma unroll
        for (int s = 0; s < 8; s++) {
            int j = j0 + (s << 3) + (lt << 1);
            acS[s].x = (j     <= capA) ? (acS[s].x + ga[s].x) * inv : -1e30f;
            acS[s].y = (j + 1 <= capA) ? (acS[s].y + ga[s].y) * inv : -1e30f;
            acS[s].z = (j     <= capB) ? (acS[s].z + gb[s].x) * inv : -1e30f;
            acS[s].w = (j + 1 <= capB) ? (acS[s].w + gb[s].y) * inv : -1e30f;
            mxA = fmaxf(mxA, fmaxf(acS[s].x, acS[s].y));
            mxB = fmaxf(mxB, fmaxf(acS[s].z, acS[s].w));
        }
        mxA = fmaxf(mxA, __shfl_xor_sync(0xffffffffu, mxA, 1));
        mxA = fmaxf(mxA, __shfl_xor_sync(0xffffffffu, mxA, 2));
        mxB = fmaxf(mxB, __shfl_xor_sync(0xffffffffu, mxB, 1));
        mxB = fmaxf(mxB, __shfl_xor_sync(0xffffffffu, mxB, 2));

        float mnA = fmaxf(mA, mxA), mnB = fmaxf(mB, mxB);
        float fA = __expf(mA - mnA), fB = __expf(mB - mnB);
        mA = mnA; mB = mnB;

        // ---- P = exp(S - m), partial sums, store P (per-warp rows) ----
        float sA = 0.f, sB = 0.f;
#pragma unroll
        for (int s = 0; s < 8; s++) {
            int c = (s << 3) + (lt << 1);
            float p0 = __expf(acS[s].x - mnA);
            float p1 = __expf(acS[s].y - mnA);
            float p2 = __expf(acS[s].z - mnB);
            float p3 = __expf(acS[s].w - mnB);
            sA += p0 + p1; sB += p2 + p3;
            Ps[(wm + g) * 68 + c]     = f2tf(p0);
            Ps[(wm + g) * 68 + c + 1] = f2tf(p1);
            Ps[(wm + g + 8) * 68 + c]     = f2tf(p2);
            Ps[(wm + g + 8) * 68 + c + 1] = f2tf(p3);
        }
        sA += __shfl_xor_sync(0xffffffffu, sA, 1);
        sA += __shfl_xor_sync(0xffffffffu, sA, 2);
        sB += __shfl_xor_sync(0xffffffffu, sB, 1);
        sB += __shfl_xor_sync(0xffffffffu, sB, 2);
        lA = lA * fA + sA;
        lB = lB * fB + sB;

#pragma unroll
        for (int n = 0; n < 16; n++) {
            on[n].x *= fA; on[n].y *= fA; on[n].z *= fB; on[n].w *= fB;
        }

        if (jt + 1 < njt) cpa_wait<1>();            // V(jt) done (K(jt+1) may be pending)
        else              cpa_wait<0>();
        __syncthreads();                            // (3) Vs visible (Ps is warp-local)

        // ---- PV mma: O += P @ V ----
#pragma unroll
        for (int kc = 0; kc < 8; kc++) {
            int kb = kc << 3;
            uint32_t a[4] = { Ps[(wm + g) * 68 + kb + lt],
                              Ps[(wm + g + 8) * 68 + kb + lt],
                              Ps[(wm + g) * 68 + kb + lt + 4],
                              Ps[(wm + g + 8) * 68 + kb + lt + 4] };
#pragma unroll
            for (int n = 0; n < 16; n++) {
                int c = (n << 3) + g;
                mma8(on[n], a, Vs[(kb + lt) * 136 + c], Vs[(kb + lt + 4) * 136 + c]);
            }
        }
    }

    // ---- epilogue: O / l -> att ----
    float ivA = 1.f / lA, ivB = 1.f / lB;
    float* ap = att + (long)z * 65536;
#pragma unroll
    for (int n = 0; n < 16; n++) {
        int c = (n << 3) + (lt << 1);
        *(float2*)(ap + (long)iA * 128 + c) = make_float2(on[n].x * ivA, on[n].y * ivA);
        *(float2*)(ap + (long)iB * 128 + c) = make_float2(on[n].z * ivB, on[n].w * ivB);
    }
}

// ---------------- Wmlp split-K, cp.async 2-stage. Grid (4, 64). ----------------
#define MLP_SMEM 70656
__global__ __launch_bounds__(256) void gemm_mlp_part(
    const float* __restrict__ A, const float* __restrict__ Bw, float* __restrict__ part)
{
    const int N = 128, K = 1024;
    extern __shared__ uint32_t sh[];
    const uint32_t sbase = (uint32_t)__cvta_generic_to_shared(sh);

    const int tid = threadIdx.x, lane = tid & 31, wid = tid >> 5;
    const int m0 = blockIdx.y << 7;
    const int kc = blockIdx.x;
    const int kbeg = kc << 8;
    float* P = part + (long)kc * 1048576;

    const int wm = (wid & 1) << 6;
    const int wn = (wid >> 1) << 5;
    const int g = lane >> 2, lt = lane & 3;
    const int am = tid >> 3, ak = (tid & 7) << 2;
    const int bk = tid >> 5, bn = (tid & 31) << 2;

    auto stage = [&](int p, int k0) {
#pragma unroll
        for (int it = 0; it < 4; it++) {
            cpa16(sbase + p * 18432 + ((am + (it << 5)) * 36 + ak) * 4,
                  A + (long)(m0 + am + (it << 5)) * K + k0 + ak);
            cpa16(sbase + 36864 + p * 16896 + ((bk + (it << 3)) * 132 + bn) * 4,
                  Bw + (long)(k0 + bk + (it << 3)) * N + bn);
        }
        cpa_commit();
    };

    float4 acc[4][4];
#pragma unroll
    for (int t = 0; t < 4; t++)
#pragma unroll
        for (int s = 0; s < 4; s++) acc[t][s] = make_float4(0.f, 0.f, 0.f, 0.f);

    stage(0, kbeg);
#pragma unroll
    for (int kq = 0; kq < 8; kq++) {
        if (kq < 7) { stage((kq + 1) & 1, kbeg + ((kq + 1) << 5)); cpa_wait<1>(); }
        else        { cpa_wait<0>(); }
        __syncthreads();
        const uint32_t* Ac = sh + (kq & 1) * 4608;
        const uint32_t* Bc = sh + 9216 + (kq & 1) * 4224;
#pragma unroll
        for (int kk = 0; kk < 4; kk++) {
            const int kb = kk << 3;
            uint32_t af[4][4];
#pragma unroll
            for (int t = 0; t < 4; t++) {
                int row = wm + (t << 4) + g;
                af[t][0] = Ac[row * 36 + kb + lt];
                af[t][1] = Ac[(row + 8) * 36 + kb + lt];
                af[t][2] = Ac[row * 36 + kb + lt + 4];
                af[t][3] = Ac[(row + 8) * 36 + kb + lt + 4];
            }
#pragma unroll
            for (int s = 0; s < 4; s++) {
                int col = wn + (s << 3) + g;
                uint32_t b0 = Bc[(kb + lt) * 132 + col];
                uint32_t b1 = Bc[(kb + lt + 4) * 132 + col];
#pragma unroll
                for (int t = 0; t < 4; t++) mma8(acc[t][s], af[t], b0, b1);
            }
        }
        __syncthreads();
    }

#pragma unroll
    for (int t = 0; t < 4; t++) {
        int r0 = m0 + wm + (t << 4) + g;
#pragma unroll
        for (int s = 0; s < 4; s++) {
            int c = wn + (s << 3) + (lt << 1);
            *(float2*)(P + (long)r0 * N + c) = make_float2(acc[t][s].x, acc[t][s].y);
            *(float2*)(P + (long)(r0 + 8) * N + c) = make_float2(acc[t][s].z, acc[t][s].w);
        }
    }
}

// ---------------- ln4: out = LayerNorm(sum(partials) + x) * gamma + beta ----------------
__global__ __launch_bounds__(256) void ln4_kernel(
    const float* __restrict__ part, const float* __restrict__ xres,
    const float* __restrict__ gamma, const float* __restrict__ beta,
    float* __restrict__ out)
{
    const int row  = (blockIdx.x << 3) + (threadIdx.x >> 5);
    const int lane = threadIdx.x & 31;
    const long off = (long)row * 128 + (lane << 2);

    float4 v = *(const float4*)(xres + off);
#pragma unroll
    for (int p = 0; p < 4; p++) {
        float4 pv = *(const float4*)(part + (long)p * 1048576 + off);
        v.x += pv.x; v.y += pv.y; v.z += pv.z; v.w += pv.w;
    }

    float s = v.x + v.y + v.z + v.w;
#pragma unroll
    for (int o = 16; o > 0; o >>= 1) s += __shfl_xor_sync(0xffffffffu, s, o);
    float mu = s * (1.0f / 128.0f);

    float dx = v.x - mu, dy = v.y - mu, dz = v.z - mu, dw = v.w - mu;
    float q = dx * dx + dy * dy + dz * dz + dw * dw;
#pragma unroll
    for (int o = 16; o > 0; o >>= 1) q += __shfl_xor_sync(0xffffffffu, q, o);
    float inv = rsqrtf(q * (1.0f / 128.0f) + 1e-5f);

    float4 g4 = *(const float4*)(gamma + (lane << 2));
    float4 b4 = *(const float4*)(beta + (lane << 2));
    float4 o4;
    o4.x = dx * inv * g4.x + b4.x;
    o4.y = dy * inv * g4.y + b4.y;
    o4.z = dz * inv * g4.z + b4.z;
    o4.w = dw * inv * g4.w + b4.w;
    *(float4*)(out + off) = o4;
}

// ---------------- launch ----------------
extern "C" void kernel_launch(void* const* d_in, const int* in_sizes, int n_in,
                              void* d_out, int out_size)
{
    const float* x     = (const float*)d_in[0];
    const float* mem   = (const float*)d_in[1];
    const float* R     = (const float*)d_in[2];
    // d_in[3] = att_mask (all ones; unused by reference)
    const float* u1    = (const float*)d_in[4];
    const float* u2    = (const float*)d_in[5];
    const float* Wq    = (const float*)d_in[6];
    const float* Wkv   = (const float*)d_in[7];
    const float* Wr    = (const float*)d_in[8];
    const float* Wmlp  = (const float*)d_in[9];
    const float* gamma = (const float*)d_in[10];
    const float* beta  = (const float*)d_in[11];
    float* out = (float*)d_out;

    float *qf, *kvf, *rf, *gg, *att, *part;
    cudaGetSymbolAddress((void**)&qf,  g_qf);
    cudaGetSymbolAddress((void**)&kvf, g_kvf);
    cudaGetSymbolAddress((void**)&rf,  g_rf);
    cudaGetSymbolAddress((void**)&gg,  g_g);
    cudaGetSymbolAddress((void**)&att, g_att);
    cudaGetSymbolAddress((void**)&part, g_part);

    cudaFuncSetAttribute(gemm3, cudaFuncAttributeMaxDynamicSharedMemorySize, G3_SMEM);
    cudaFuncSetAttribute(gemm_nt_g, cudaFuncAttributeMaxDynamicSharedMemorySize, GNT_SMEM);
    cudaFuncSetAttribute(flash_pv, cudaFuncAttributeMaxDynamicSharedMemorySize, FLASH_SMEM);
    cudaFuncSetAttribute(gemm_mlp_part, cudaFuncAttributeMaxDynamicSharedMemorySize, MLP_SMEM);

    // 1) kvf | qf | rf in one co-scheduled launch (cp.async 2-stage)
    gemm3<<<2624, 256, G3_SMEM>>>(x, mem, R, Wq, Wkv, Wr, qf, kvf, rf);
    // 2) G = (q + u2) @ r^T per z (banded tiles only; cp.async 2-stage)
    gemm_nt_g<<<dim3(8, 4, 128), 256, GNT_SMEM>>>(qf, rf, u2, gg);
    // 3) fused: S = ((q+u1)K^T + gather(G))/sqrt(d) -> online softmax -> att = P@V
    flash_pv<<<dim3(8, 128), 128, FLASH_SMEM>>>(qf, kvf, gg, u1, att);
    // 4) Wmlp split-K partials (cp.async 2-stage)
    gemm_mlp_part<<<dim3(4, 64), 256, MLP_SMEM>>>(att, Wmlp, part);
    // 5) out = LayerNorm(sum(partials) + x) * gamma + beta
    ln4_kernel<<<1024, 256>>>(part, x, gamma, beta, out);
}

// round 17
// speedup vs baseline: 1.1283x; 1.1283x over previous
#include <cuda_runtime.h>
#include <math.h>
#include <stdint.h>

// Problem constants: B=16, SEG=512, MEM=512, TOTAL=1024, MD=128, H=8, D=128

// ---------------- scratch ----------------
__device__ float    g_qf [16 * 512 * 1024];        // x@Wq              32 MB
__device__ uint32_t g_kb [8388608];                // K half of kvf, bf16 pairs  32 MB
__device__ float    g_vf [16 * 1024 * 128 * 8];    // V half of kvf (fp32)       64 MB
__device__ float    g_rf [1024 * 1024];            // R@Wr               4 MB
__device__ float    g_g  [128ll * 512 * 1024];     // G=(q+u2)@r^T     256 MB
__device__ float    g_att[16 * 512 * 1024];        // attention out     32 MB
__device__ float    g_part[4 * 8192 * 128];        // Wmlp split-K partials 16 MB

// ---------------- helpers ----------------
__device__ __forceinline__ uint32_t f2tf(float f) {
    uint32_t u; asm("cvt.rna.tf32.f32 %0, %1;" : "=r"(u) : "f"(f)); return u;
}
__device__ __forceinline__ uint32_t pbf2(float lo, float hi) {
    uint32_t u; asm("cvt.rn.bf16x2.f32 %0, %1, %2;" : "=r"(u) : "f"(hi), "f"(lo)); return u;
}
__device__ __forceinline__ void mma8(float4& c, const uint32_t a[4], uint32_t b0, uint32_t b1) {
    asm volatile("mma.sync.aligned.m16n8k8.row.col.f32.tf32.tf32.f32 "
        "{%0,%1,%2,%3}, {%4,%5,%6,%7}, {%8,%9}, {%0,%1,%2,%3};"
        : "+f"(c.x), "+f"(c.y), "+f"(c.z), "+f"(c.w)
        : "r"(a[0]), "r"(a[1]), "r"(a[2]), "r"(a[3]), "r"(b0), "r"(b1));
}
__device__ __forceinline__ void mma16(float4& c, const uint32_t a[4], uint32_t b0, uint32_t b1) {
    asm volatile("mma.sync.aligned.m16n8k16.row.col.f32.bf16.bf16.f32 "
        "{%0,%1,%2,%3}, {%4,%5,%6,%7}, {%8,%9}, {%0,%1,%2,%3};"
        : "+f"(c.x), "+f"(c.y), "+f"(c.z), "+f"(c.w)
        : "r"(a[0]), "r"(a[1]), "r"(a[2]), "r"(a[3]), "r"(b0), "r"(b1));
}
__device__ __forceinline__ void cpa16(uint32_t saddr, const void* g) {
    asm volatile("cp.async.cg.shared.global [%0], [%1], 16;" :: "r"(saddr), "l"(g));
}
__device__ __forceinline__ void cpa_commit() {
    asm volatile("cp.async.commit_group;");
}
template <int N> __device__ __forceinline__ void cpa_wait() {
    asm volatile("cp.async.wait_group %0;" :: "n"(N));
}

// ---------------- gemm3: (K->bf16, V) | qf | rf, cp.async 2-stage ----------------
// flat bid: [0,2048) kv tiles (rows<8192 => K bf16; else V fp32), [2048,2560) qf, [2560,2624) rf
#define G3_SMEM 70656
__global__ __launch_bounds__(256) void gemm3(
    const float* __restrict__ x, const float* __restrict__ mem, const float* __restrict__ R,
    const float* __restrict__ Wq, const float* __restrict__ Wkv, const float* __restrict__ Wr,
    float* __restrict__ qf, uint32_t* __restrict__ kb, float* __restrict__ vf,
    float* __restrict__ rf)
{
    extern __shared__ uint32_t sh[];
    const uint32_t sbase = (uint32_t)__cvta_generic_to_shared(sh);

    const int tid = threadIdx.x, lane = tid & 31, wid = tid >> 5;
    const int g = lane >> 2, lt = lane & 3;
    const int wm = (wid & 1) << 6;
    const int wn = (wid >> 1) << 5;
    const int am = tid >> 3, ak = (tid & 7) << 2;
    const int bk = tid >> 5, bn = (tid & 31) << 2;

    const int bid = blockIdx.x;
    int N, m0, n0, kvmode = 0;
    const float* Bw;
    float* C = nullptr;
    const float* aptr[4];

    if (bid < 2048) {                       // kvf = concat(mem,x) @ Wkv
        N = 2048; Bw = Wkv;
        m0 = (bid >> 4) << 7; n0 = (bid & 15) << 7;
        kvmode = (m0 < 8192) ? 1 : 2;       // 1 = K (bf16), 2 = V (fp32)
        C = vf;
#pragma unroll
        for (int it = 0; it < 4; it++) {
            int row = m0 + am + (it << 5);
            int b = row >> 10, loc = row & 1023;
            aptr[it] = (loc < 512) ? (mem + (long)b * 65536 + (long)loc * 128)
                                   : (x   + (long)b * 65536 + (long)(loc - 512) * 128);
        }
    } else if (bid < 2560) {                // qf = x @ Wq
        int t = bid - 2048;
        N = 1024; Bw = Wq; C = qf;
        m0 = (t >> 3) << 7; n0 = (t & 7) << 7;
#pragma unroll
        for (int it = 0; it < 4; it++)
            aptr[it] = x + (long)(m0 + am + (it << 5)) * 128;
    } else {                                // rf = R @ Wr
        int t = bid - 2560;
        N = 1024; Bw = Wr; C = rf;
        m0 = (t >> 3) << 7; n0 = (t & 7) << 7;
#pragma unroll
        for (int it = 0; it < 4; it++)
            aptr[it] = R + (long)(m0 + am + (it << 5)) * 128;
    }

    auto stage = [&](int p, int k0) {
#pragma unroll
        for (int it = 0; it < 4; it++) {
            cpa16(sbase + p * 18432 + ((am + (it << 5)) * 36 + ak) * 4,
                  aptr[it] + k0 + ak);
            cpa16(sbase + 36864 + p * 16896 + ((bk + (it << 3)) * 132 + bn) * 4,
                  Bw + (long)(k0 + bk + (it << 3)) * N + n0 + bn);
        }
        cpa_commit();
    };

    float4 acc[4][4];
#pragma unroll
    for (int t = 0; t < 4; t++)
#pragma unroll
        for (int s = 0; s < 4; s++) acc[t][s] = make_float4(0.f, 0.f, 0.f, 0.f);

    stage(0, 0);
#pragma unroll
    for (int kq = 0; kq < 4; kq++) {
        if (kq < 3) { stage((kq + 1) & 1, (kq + 1) << 5); cpa_wait<1>(); }
        else        { cpa_wait<0>(); }
        __syncthreads();
        const uint32_t* Ac = sh + (kq & 1) * 4608;
        const uint32_t* Bc = sh + 9216 + (kq & 1) * 4224;
#pragma unroll
        for (int kk = 0; kk < 4; kk++) {
            const int kb2 = kk << 3;
            uint32_t af[4][4];
#pragma unroll
            for (int t = 0; t < 4; t++) {
                int row = wm + (t << 4) + g;
                af[t][0] = Ac[row * 36 + kb2 + lt];
                af[t][1] = Ac[(row + 8) * 36 + kb2 + lt];
                af[t][2] = Ac[row * 36 + kb2 + lt + 4];
                af[t][3] = Ac[(row + 8) * 36 + kb2 + lt + 4];
            }
#pragma unroll
            for (int s = 0; s < 4; s++) {
                int col = wn + (s << 3) + g;
                uint32_t b0 = Bc[(kb2 + lt) * 132 + col];
                uint32_t b1 = Bc[(kb2 + lt + 4) * 132 + col];
#pragma unroll
                for (int t = 0; t < 4; t++) mma8(acc[t][s], af[t], b0, b1);
            }
        }
        __syncthreads();
    }

    if (kvmode == 1) {
        // K rows -> bf16 pairs (row*2048 + c even)
#pragma unroll
        for (int t = 0; t < 4; t++) {
            int r0 = m0 + wm + (t << 4) + g;
#pragma unroll
            for (int s = 0; s < 4; s++) {
                int c = n0 + wn + (s << 3) + (lt << 1);
                kb[((long)r0 * 2048 + c) >> 1]       = pbf2(acc[t][s].x, acc[t][s].y);
                kb[((long)(r0 + 8) * 2048 + c) >> 1] = pbf2(acc[t][s].z, acc[t][s].w);
            }
        }
    } else {
        int mo = (kvmode == 2) ? m0 - 8192 : m0;
#pragma unroll
        for (int t = 0; t < 4; t++) {
            int r0 = mo + wm + (t << 4) + g;
#pragma unroll
            for (int s = 0; s < 4; s++) {
                int c = n0 + wn + (s << 3) + (lt << 1);
                *(float2*)(C + (long)r0 * N + c) = make_float2(acc[t][s].x, acc[t][s].y);
                *(float2*)(C + (long)(r0 + 8) * N + c) = make_float2(acc[t][s].z, acc[t][s].w);
            }
        }
    }
}

// ---------------- G = (q + u2) @ r^T, cp.async 2-stage ----------------
#define GNT_SMEM 73728
__global__ __launch_bounds__(256) void gemm_nt_g(
    const float* __restrict__ qf, const float* __restrict__ rf,
    const float* __restrict__ U2, float* __restrict__ Gg)
{
    const int r0 = blockIdx.y << 7, c0 = blockIdx.x << 7;
    if (r0 + c0 + 254 < 511) return;     // never-used region of G
    const int z = blockIdx.z, h = z & 7;
    const float* A  = qf + (long)z * 65536;
    const float* Bm = rf + (long)h * 131072;
    float*       G  = Gg + (long)z * 524288;

    extern __shared__ uint32_t sh[];
    const uint32_t sbase = (uint32_t)__cvta_generic_to_shared(sh);
    __shared__ float u2s[128];

    const int tid = threadIdx.x, lane = tid & 31, wid = tid >> 5;
    const int wm = (wid & 1) << 6;
    const int wn = (wid >> 1) << 5;
    const int g = lane >> 2, lt = lane & 3;
    const int am = tid >> 3, ak = (tid & 7) << 2;

    if (tid < 128) u2s[tid] = U2[(h << 7) + tid];

    auto stage = [&](int p, int k0) {
#pragma unroll
        for (int it = 0; it < 4; it++) {
            cpa16(sbase + p * 18432 + ((am + (it << 5)) * 36 + ak) * 4,
                  A + (long)(r0 + am + (it << 5)) * 128 + k0 + ak);
            cpa16(sbase + 36864 + p * 18432 + ((am + (it << 5)) * 36 + ak) * 4,
                  Bm + (long)(c0 + am + (it << 5)) * 128 + k0 + ak);
        }
        cpa_commit();
    };

    float4 acc[4][4];
#pragma unroll
    for (int t = 0; t < 4; t++)
#pragma unroll
        for (int s = 0; s < 4; s++) acc[t][s] = make_float4(0.f, 0.f, 0.f, 0.f);

    stage(0, 0);
#pragma unroll
    for (int kq = 0; kq < 4; kq++) {
        const int k0 = kq << 5;
        if (kq < 3) { stage((kq + 1) & 1, (kq + 1) << 5); cpa_wait<1>(); }
        else        { cpa_wait<0>(); }
        __syncthreads();
        const uint32_t* Ac = sh + (kq & 1) * 4608;
        const uint32_t* Bc = sh + 9216 + (kq & 1) * 4608;
#pragma unroll
        for (int kk = 0; kk < 4; kk++) {
            const int kb2 = kk << 3;
            float uLo = u2s[k0 + kb2 + lt], uHi = u2s[k0 + kb2 + lt + 4];
            uint32_t af[4][4];
#pragma unroll
            for (int t = 0; t < 4; t++) {
                int row = wm + (t << 4) + g;
                af[t][0] = f2tf(__uint_as_float(Ac[row * 36 + kb2 + lt]) + uLo);
                af[t][1] = f2tf(__uint_as_float(Ac[(row + 8) * 36 + kb2 + lt]) + uLo);
                af[t][2] = f2tf(__uint_as_float(Ac[row * 36 + kb2 + lt + 4]) + uHi);
                af[t][3] = f2tf(__uint_as_float(Ac[(row + 8) * 36 + kb2 + lt + 4]) + uHi);
            }
#pragma unroll
            for (int s = 0; s < 4; s++) {
                int n = (wn + (s << 3) + g) * 36 + kb2 + lt;
                uint32_t b0 = Bc[n], b1 = Bc[n + 4];
#pragma unroll
                for (int t = 0; t < 4; t++) mma8(acc[t][s], af[t], b0, b1);
            }
        }
        __syncthreads();
    }

#pragma unroll
    for (int t = 0; t < 4; t++) {
        int rr = r0 + wm + (t << 4) + g;
#pragma unroll
        for (int s = 0; s < 4; s++) {
            int c = c0 + wn + (s << 3) + (lt << 1);
            *(float2*)(G + (long)rr * 1024 + c) = make_float2(acc[t][s].x, acc[t][s].y);
            *(float2*)(G + (long)(rr + 8) * 1024 + c) = make_float2(acc[t][s].z, acc[t][s].w);
        }
    }
}

// ---------------- fused flash: bf16 AC + tf32 PV ----------------
// Grid (8 i-tiles, 128 z); 128 threads / 4 warps; warp owns 16 full rows.
// Smem: Ps[64][68] u32 @0 (17408) | Ksp[64][68] bf16-pairs @17408 (17408) | Vs[64][136] @34816 (34816). 69632 B.
#define FLASH_SMEM 69632

__global__ __launch_bounds__(128) void flash_pv(
    const float* __restrict__ qf, const uint32_t* __restrict__ kbg,
    const float* __restrict__ vfg, const float* __restrict__ Gg,
    const float* __restrict__ U1, float* __restrict__ att)
{
    extern __shared__ char dsm[];
    uint32_t* Ps  = (uint32_t*)dsm;                 // [64][68] tf32 P
    uint32_t* Ksp = (uint32_t*)(dsm + 17408);       // [64][68] bf16 pairs
    uint32_t* Vs  = (uint32_t*)(dsm + 34816);       // [64][136] fp32-as-tf32
    const uint32_t ks_s = (uint32_t)__cvta_generic_to_shared(Ksp);
    const uint32_t vs_s = (uint32_t)__cvta_generic_to_shared(Vs);

    const int it = 7 - blockIdx.x;                  // heavy tiles first
    const int z = blockIdx.y, h = z & 7;
    const int i0 = it << 6;
    const float* Q  = qf  + (long)z * 65536;
    const char*  Kb = (const char*)kbg + (long)z * 262144;   // bf16 bytes
    const float* Vg = vfg + (long)z * 131072;
    const float* Gz = Gg  + (long)z * 524288;
    const float* u1 = U1  + (h << 7);

    const int tid = threadIdx.x, lane = tid & 31, w = tid >> 5;
    const int g = lane >> 2, lt = lane & 3;
    const int wm = w << 4;
    const int iA = i0 + wm + g, iB = iA + 8;

    const int sr = tid >> 1, hh = tid & 1;          // K staging: 64 rows, 2 thr/row
    const int sc0 = hh << 2;                        // V staging col base

    // prologue: async-stage K(0) (bf16 rows = 256 B)
#pragma unroll
    for (int f = 0; f < 8; f++) {
        cpa16(ks_s + sr * 272 + hh * 128 + (f << 4),
              Kb + (long)sr * 256 + hh * 128 + (f << 4));
    }
    cpa_commit();

    // resident bf16 (q+u1) A-fragments: 8 kc x 4 regs
    uint32_t Qreg[32];
#pragma unroll
    for (int kc = 0; kc < 8; kc++) {
        int k0 = kc << 4;
        float2 uA = *(const float2*)(u1 + k0 + (lt << 1));
        float2 uB = *(const float2*)(u1 + k0 + (lt << 1) + 8);
        float2 qa = *(const float2*)(Q + (long)iA * 128 + k0 + (lt << 1));
        float2 qb = *(const float2*)(Q + (long)iB * 128 + k0 + (lt << 1));
        float2 qc = *(const float2*)(Q + (long)iA * 128 + k0 + (lt << 1) + 8);
        float2 qd = *(const float2*)(Q + (long)iB * 128 + k0 + (lt << 1) + 8);
        Qreg[kc * 4 + 0] = pbf2(qa.x + uA.x, qa.y + uA.y);
        Qreg[kc * 4 + 1] = pbf2(qb.x + uA.x, qb.y + uA.y);
        Qreg[kc * 4 + 2] = pbf2(qc.x + uB.x, qc.y + uB.y);
        Qreg[kc * 4 + 3] = pbf2(qd.x + uB.x, qd.y + uB.y);
    }

    float4 on[16];
#pragma unroll
    for (int n = 0; n < 16; n++) on[n] = make_float4(0.f, 0.f, 0.f, 0.f);
    float mA = -1e30f, mB = -1e30f, lA = 0.f, lB = 0.f;

    const float inv = 0.08838834764831845f;         // 1/sqrt(128)
    const float* GA = Gz + (long)iA * 1024 + 511 - iA;
    const float* GB = Gz + (long)iB * 1024 + 511 - iB;
    const int capA = iA + 512, capB = iB + 512;
    const int njt = it + 9;

    for (int jt = 0; jt < njt; jt++) {
        const int j0 = jt << 6;

        cpa_wait<0>();                              // K(jt) complete
        __syncthreads();                            // (1) prev PV done + Ks visible

        // issue V(jt) async — overlaps AC mma
#pragma unroll
        for (int f = 0; f < 16; f++) {
            int c = sc0 + (f << 3);
            cpa16(vs_s + (sr * 136 + c) * 4, Vg + (long)(j0 + sr) * 128 + c);
        }
        cpa_commit();

        // prefetch G rows (guarded) — latency hidden under AC mma
        float2 ga[8], gb[8];
#pragma unroll
        for (int s = 0; s < 8; s++) {
            int j = j0 + (s << 3) + (lt << 1);
            ga[s].x = (j     <= capA) ? GA[j]     : 0.f;
            ga[s].y = (j + 1 <= capA) ? GA[j + 1] : 0.f;
            gb[s].x = (j     <= capB) ? GB[j]     : 0.f;
            gb[s].y = (j + 1 <= capB) ? GB[j + 1] : 0.f;
        }

        // ---- AC mma (bf16 m16n8k16) ----
        float4 acS[8];
#pragma unroll
        for (int s = 0; s < 8; s++) acS[s] = make_float4(0.f, 0.f, 0.f, 0.f);
#pragma unroll
        for (int kc = 0; kc < 8; kc++) {
            const uint32_t* a = &Qreg[kc << 2];
            int kp = kc << 3;
#pragma unroll
            for (int s = 0; s < 8; s++) {
                int n = ((s << 3) + g) * 68 + kp + lt;
                mma16(acS[s], a, Ksp[n], Ksp[n + 4]);
            }
        }

        __syncthreads();                            // (2) all warps done reading Ks
        if (jt + 1 < njt) {                         // issue K(jt+1) — overlaps softmax + PV
            const int jn = (jt + 1) << 6;
#pragma unroll
            for (int f = 0; f < 8; f++) {
                cpa16(ks_s + sr * 272 + hh * 128 + (f << 4),
                      Kb + (long)(jn + sr) * 256 + hh * 128 + (f << 4));
            }
            cpa_commit();
        }

        // ---- add G, scale, mask; row max ----
        float mxA = -1e30f, mxB = -1e30f;
#pragma unroll
        for (int s = 0; s < 8; s++) {
            int j = j0 + (s << 3) + (lt << 1);
            acS[s].x = (j     <= capA) ? (acS[s].x + ga[s].x) * inv : -1e30f;
            acS[s].y = (j + 1 <= capA) ? (acS[s].y + ga[s].y) * inv : -1e30f;
            acS[s].z = (j     <= capB) ? (acS[s].z + gb[s].x) * inv : -1e30f;
            acS[s].w = (j + 1 <= capB) ? (acS[s].w + gb[s].y) * inv : -1e30f;
            mxA = fmaxf(mxA, fmaxf(acS[s].x, acS[s].y));
            mxB = fmaxf(mxB, fmaxf(acS[s].z, acS[s].w));
        }
        mxA = fmaxf(mxA, __shfl_xor_sync(0xffffffffu, mxA, 1));
        mxA = fmaxf(mxA, __shfl_xor_sync(0xffffffffu, mxA, 2));
        mxB = fmaxf(mxB, __shfl_xor_sync(0xffffffffu, mxB, 1));
        mxB = fmaxf(mxB, __shfl_xor_sync(0xffffffffu, mxB, 2));

        float mnA = fmaxf(mA, mxA), mnB = fmaxf(mB, mxB);
        float fA = __expf(mA - mnA), fB = __expf(mB - mnB);
        mA = mnA; mB = mnB;

        // ---- P = exp(S - m), partial sums, store P (per-warp rows, tf32) ----
        float sA = 0.f, sB = 0.f;
#pragma unroll
        for (int s = 0; s < 8; s++) {
            int c = (s << 3) + (lt << 1);
            float p0 = __expf(acS[s].x - mnA);
            float p1 = __expf(acS[s].y - mnA);
            float p2 = __expf(acS[s].z - mnB);
            float p3 = __expf(acS[s].w - mnB);
            sA += p0 + p1; sB += p2 + p3;
            Ps[(wm + g) * 68 + c]     = f2tf(p0);
            Ps[(wm + g) * 68 + c + 1] = f2tf(p1);
            Ps[(wm + g + 8) * 68 + c]     = f2tf(p2);
            Ps[(wm + g + 8) * 68 + c + 1] = f2tf(p3);
        }
        sA += __shfl_xor_sync(0xffffffffu, sA, 1);
        sA += __shfl_xor_sync(0xffffffffu, sA, 2);
        sB += __shfl_xor_sync(0xffffffffu, sB, 1);
        sB += __shfl_xor_sync(0xffffffffu, sB, 2);
        lA = lA * fA + sA;
        lB = lB * fB + sB;

#pragma unroll
        for (int n = 0; n < 16; n++) {
            on[n].x *= fA; on[n].y *= fA; on[n].z *= fB; on[n].w *= fB;
        }

        if (jt + 1 < njt) cpa_wait<1>();            // V(jt) done (K(jt+1) pending)
        else              cpa_wait<0>();
        __syncthreads();                            // (3) Vs visible

        // ---- PV mma (tf32): O += P @ V ----
#pragma unroll
        for (int kc = 0; kc < 8; kc++) {
            int kb2 = kc << 3;
            uint32_t a[4] = { Ps[(wm + g) * 68 + kb2 + lt],
                              Ps[(wm + g + 8) * 68 + kb2 + lt],
                              Ps[(wm + g) * 68 + kb2 + lt + 4],
                              Ps[(wm + g + 8) * 68 + kb2 + lt + 4] };
#pragma unroll
            for (int n = 0; n < 16; n++) {
                int c = (n << 3) + g;
                mma8(on[n], a, Vs[(kb2 + lt) * 136 + c], Vs[(kb2 + lt + 4) * 136 + c]);
            }
        }
    }

    // ---- epilogue: O / l -> att ----
    float ivA = 1.f / lA, ivB = 1.f / lB;
    float* ap = att + (long)z * 65536;
#pragma unroll
    for (int n = 0; n < 16; n++) {
        int c = (n << 3) + (lt << 1);
        *(float2*)(ap + (long)iA * 128 + c) = make_float2(on[n].x * ivA, on[n].y * ivA);
        *(float2*)(ap + (long)iB * 128 + c) = make_float2(on[n].z * ivB, on[n].w * ivB);
    }
}

// ---------------- Wmlp split-K, cp.async 2-stage. Grid (4, 64). ----------------
#define MLP_SMEM 70656
__global__ __launch_bounds__(256) void gemm_mlp_part(
    const float* __restrict__ A, const float* __restrict__ Bw, float* __restrict__ part)
{
    const int N = 128, K = 1024;
    extern __shared__ uint32_t sh[];
    const uint32_t sbase = (uint32_t)__cvta_generic_to_shared(sh);

    const int tid = threadIdx.x, lane = tid & 31, wid = tid >> 5;
    const int m0 = blockIdx.y << 7;
    const int kc = blockIdx.x;
    const int kbeg = kc << 8;
    float* P = part + (long)kc * 1048576;

    const int wm = (wid & 1) << 6;
    const int wn = (wid >> 1) << 5;
    const int g = lane >> 2, lt = lane & 3;
    const int am = tid >> 3, ak = (tid & 7) << 2;
    const int bk = tid >> 5, bn = (tid & 31) << 2;

    auto stage = [&](int p, int k0) {
#pragma unroll
        for (int it = 0; it < 4; it++) {
            cpa16(sbase + p * 18432 + ((am + (it << 5)) * 36 + ak) * 4,
                  A + (long)(m0 + am + (it << 5)) * K + k0 + ak);
            cpa16(sbase + 36864 + p * 16896 + ((bk + (it << 3)) * 132 + bn) * 4,
                  Bw + (long)(k0 + bk + (it << 3)) * N + bn);
        }
        cpa_commit();
    };

    float4 acc[4][4];
#pragma unroll
    for (int t = 0; t < 4; t++)
#pragma unroll
        for (int s = 0; s < 4; s++) acc[t][s] = make_float4(0.f, 0.f, 0.f, 0.f);

    stage(0, kbeg);
#pragma unroll
    for (int kq = 0; kq < 8; kq++) {
        if (kq < 7) { stage((kq + 1) & 1, kbeg + ((kq + 1) << 5)); cpa_wait<1>(); }
        else        { cpa_wait<0>(); }
        __syncthreads();
        const uint32_t* Ac = sh + (kq & 1) * 4608;
        const uint32_t* Bc = sh + 9216 + (kq & 1) * 4224;
#pragma unroll
        for (int kk = 0; kk < 4; kk++) {
            const int kb2 = kk << 3;
            uint32_t af[4][4];
#pragma unroll
            for (int t = 0; t < 4; t++) {
                int row = wm + (t << 4) + g;
                af[t][0] = Ac[row * 36 + kb2 + lt];
                af[t][1] = Ac[(row + 8) * 36 + kb2 + lt];
                af[t][2] = Ac[row * 36 + kb2 + lt + 4];
                af[t][3] = Ac[(row + 8) * 36 + kb2 + lt + 4];
            }
#pragma unroll
            for (int s = 0; s < 4; s++) {
                int col = wn + (s << 3) + g;
                uint32_t b0 = Bc[(kb2 + lt) * 132 + col];
                uint32_t b1 = Bc[(kb2 + lt + 4) * 132 + col];
#pragma unroll
                for (int t = 0; t < 4; t++) mma8(acc[t][s], af[t], b0, b1);
            }
        }
        __syncthreads();
    }

#pragma unroll
    for (int t = 0; t < 4; t++) {
        int r0 = m0 + wm + (t << 4) + g;
#pragma unroll
        for (int s = 0; s < 4; s++) {
            int c = wn + (s << 3) + (lt << 1);
            *(float2*)(P + (long)r0 * N + c) = make_float2(acc[t][s].x, acc[t][s].y);
            *(float2*)(P + (long)(r0 + 8) * N + c) = make_float2(acc[t][s].z, acc[t][s].w);
        }
    }
}

// ---------------- ln4: out = LayerNorm(sum(partials) + x) * gamma + beta ----------------
__global__ __launch_bounds__(256) void ln4_kernel(
    const float* __restrict__ part, const float* __restrict__ xres,
    const float* __restrict__ gamma, const float* __restrict__ beta,
    float* __restrict__ out)
{
    const int row  = (blockIdx.x << 3) + (threadIdx.x >> 5);
    const int lane = threadIdx.x & 31;
    const long off = (long)row * 128 + (lane << 2);

    float4 v = *(const float4*)(xres + off);
#pragma unroll
    for (int p = 0; p < 4; p++) {
        float4 pv = *(const float4*)(part + (long)p * 1048576 + off);
        v.x += pv.x; v.y += pv.y; v.z += pv.z; v.w += pv.w;
    }

    float s = v.x + v.y + v.z + v.w;
#pragma unroll
    for (int o = 16; o > 0; o >>= 1) s += __shfl_xor_sync(0xffffffffu, s, o);
    float mu = s * (1.0f / 128.0f);

    float dx = v.x - mu, dy = v.y - mu, dz = v.z - mu, dw = v.w - mu;
    float q = dx * dx + dy * dy + dz * dz + dw * dw;
#pragma unroll
    for (int o = 16; o > 0; o >>= 1) q += __shfl_xor_sync(0xffffffffu, q, o);
    float inv = rsqrtf(q * (1.0f / 128.0f) + 1e-5f);

    float4 g4 = *(const float4*)(gamma + (lane << 2));
    float4 b4 = *(const float4*)(beta + (lane << 2));
    float4 o4;
    o4.x = dx * inv * g4.x + b4.x;
    o4.y = dy * inv * g4.y + b4.y;
    o4.z = dz * inv * g4.z + b4.z;
    o4.w = dw * inv * g4.w + b4.w;
    *(float4*)(out + off) = o4;
}

// ---------------- launch ----------------
extern "C" void kernel_launch(void* const* d_in, const int* in_sizes, int n_in,
                              void* d_out, int out_size)
{
    const float* x     = (const float*)d_in[0];
    const float* mem   = (const float*)d_in[1];
    const float* R     = (const float*)d_in[2];
    // d_in[3] = att_mask (all ones; unused by reference)
    const float* u1    = (const float*)d_in[4];
    const float* u2    = (const float*)d_in[5];
    const float* Wq    = (const float*)d_in[6];
    const float* Wkv   = (const float*)d_in[7];
    const float* Wr    = (const float*)d_in[8];
    const float* Wmlp  = (const float*)d_in[9];
    const float* gamma = (const float*)d_in[10];
    const float* beta  = (const float*)d_in[11];
    float* out = (float*)d_out;

    float *qf, *vf, *rf, *gg, *att, *part;
    uint32_t* kb;
    cudaGetSymbolAddress((void**)&qf,  g_qf);
    cudaGetSymbolAddress((void**)&kb,  g_kb);
    cudaGetSymbolAddress((void**)&vf,  g_vf);
    cudaGetSymbolAddress((void**)&rf,  g_rf);
    cudaGetSymbolAddress((void**)&gg,  g_g);
    cudaGetSymbolAddress((void**)&att, g_att);
    cudaGetSymbolAddress((void**)&part, g_part);

    cudaFuncSetAttribute(gemm3, cudaFuncAttributeMaxDynamicSharedMemorySize, G3_SMEM);
    cudaFuncSetAttribute(gemm_nt_g, cudaFuncAttributeMaxDynamicSharedMemorySize, GNT_SMEM);
    cudaFuncSetAttribute(flash_pv, cudaFuncAttributeMaxDynamicSharedMemorySize, FLASH_SMEM);
    cudaFuncSetAttribute(gemm_mlp_part, cudaFuncAttributeMaxDynamicSharedMemorySize, MLP_SMEM);

    // 1) K(bf16)+V | qf | rf in one co-scheduled launch (cp.async 2-stage)
    gemm3<<<2624, 256, G3_SMEM>>>(x, mem, R, Wq, Wkv, Wr, qf, kb, vf, rf);
    // 2) G = (q + u2) @ r^T per z (banded tiles only; cp.async 2-stage)
    gemm_nt_g<<<dim3(8, 4, 128), 256, GNT_SMEM>>>(qf, rf, u2, gg);
    // 3) fused: bf16 AC + gather(G) -> online softmax -> tf32 P@V
    flash_pv<<<dim3(8, 128), 128, FLASH_SMEM>>>(qf, kb, vf, gg, u1, att);
    // 4) Wmlp split-K partials (cp.async 2-stage)
    gemm_mlp_part<<<dim3(4, 64), 256, MLP_SMEM>>>(att, Wmlp, part);
    // 5) out = LayerNorm(sum(partials) + x) * gamma + beta
    ln4_kernel<<<1024, 256>>>(part, x, gamma, beta, out);
}